// round 14
// baseline (speedup 1.0000x reference)
#include <cuda_runtime.h>
#include <cuda_bf16.h>
#include <cuda_fp8.h>
#include <math.h>
#include <stdint.h>

// Problem constants
#define BB    64
#define MAXT  511
#define TP1   512
#define SDIM  1024
#define HDIM  4096

// Tiling (fp8: KC = 128 k-elements = 128 bytes per row-chunk)
#define MT       128                  // rows per item (CTA tile M)
#define TILES_PER_B 4
#define KC       128
#define NCHUNK   (SDIM/KC)            // 8 chunks per nt
#define NT       256                  // H cols per n-tile
#define NNT      (HDIM/NT)            // 16
#define NITEMS   (NNT*BB*TILES_PER_B) // 4096 items: (nt, b, tile) nt-major
#define THREADS  512                  // 16 warps: 4 warp_m x 4 warp_n, each 32x64
#define GRID     148                  // persistent, 1 CTA/SM
#define NSTAGE   4

// SMEM layout (bytes)
#define A_OFF(s)  ((s)*16384)             // 4 x 16 KB (128 rows x 128B)
#define B_OFF(s)  (65536 + (s)*32768)     // 4 x 32 KB (256 rows x 128B)
#define LOG_OFF   196608                  // 128*4 floats
#define ITEM_OFF  198656
#define SMEM_BYTES 198912

#define SW128(x) ((x) ^ (((x) >> 3) & 0x70))

__device__ uint8_t g_sbf[(size_t)BB * TP1 * SDIM];   // 33.5 MB: s in e4m3
__device__ uint8_t g_w1t[(size_t)HDIM * SDIM];       // 4 MB  : W1^T e4m3
__device__ float   g_logits[(size_t)BB * TP1 * 4];   // 512 KB partial logits
__device__ float   g_post[BB];
__device__ unsigned g_counter;

// ---------------- helpers ----------------
__device__ __forceinline__ uint32_t smem_u32(const void* p) {
    uint32_t a;
    asm("{ .reg .u64 t; cvta.to.shared.u64 t, %1; cvt.u32.u64 %0, t; }" : "=r"(a) : "l"(p));
    return a;
}
__device__ __forceinline__ uint32_t fp8x4(float a, float b, float c, float d) {
    __nv_fp8x2_storage_t lo = __nv_cvt_float2_to_fp8x2(make_float2(a, b),
                                                       __NV_SATFINITE, __NV_E4M3);
    __nv_fp8x2_storage_t hi = __nv_cvt_float2_to_fp8x2(make_float2(c, d),
                                                       __NV_SATFINITE, __NV_E4M3);
    return (uint32_t)lo | ((uint32_t)hi << 16);
}
__device__ __forceinline__ void cp16(uint32_t dst, const void* src) {
    asm volatile("cp.async.cg.shared.global [%0], [%1], 16;" :: "r"(dst), "l"(src));
}
__device__ __forceinline__ void ldsm_x4(uint32_t* r, uint32_t addr) {
    asm volatile("ldmatrix.sync.aligned.m8n8.x4.shared.b16 {%0,%1,%2,%3}, [%4];"
                 : "=r"(r[0]), "=r"(r[1]), "=r"(r[2]), "=r"(r[3]) : "r"(addr));
}
__device__ __forceinline__ void mma16832(float* d, const uint32_t* a,
                                         uint32_t b0, uint32_t b1) {
    asm volatile("mma.sync.aligned.m16n8k32.row.col.f32.e4m3.e4m3.f32 "
                 "{%0,%1,%2,%3}, {%4,%5,%6,%7}, {%8,%9}, {%0,%1,%2,%3};"
                 : "+f"(d[0]), "+f"(d[1]), "+f"(d[2]), "+f"(d[3])
                 : "r"(a[0]), "r"(a[1]), "r"(a[2]), "r"(a[3]), "r"(b0), "r"(b1));
}

// ---------------- prepass kernels ----------------
extern "C" __global__ void init_counter() { g_counter = 0u; }

extern "C" __global__ void zero_logits() {
    ((float4*)g_logits)[blockIdx.x * 256 + threadIdx.x] = make_float4(0.f, 0.f, 0.f, 0.f);
}

extern "C" __global__ void s_cvt(const float* __restrict__ s) {
    size_t i = (size_t)blockIdx.x * 256 + threadIdx.x;
    const float4* p = (const float4*)s + i * 4;
    float4 v0 = p[0], v1 = p[1], v2 = p[2], v3 = p[3];
    uint4 o;
    o.x = fp8x4(v0.x, v0.y, v0.z, v0.w);
    o.y = fp8x4(v1.x, v1.y, v1.z, v1.w);
    o.z = fp8x4(v2.x, v2.y, v2.z, v2.w);
    o.w = fp8x4(v3.x, v3.y, v3.z, v3.w);
    ((uint4*)g_sbf)[i] = o;
}

extern "C" __global__ void w1_transpose(const float* __restrict__ W1) {
    __shared__ float tile[32][33];
    int n0 = blockIdx.x * 32, k0 = blockIdx.y * 32;
    int tx = threadIdx.x, ty = threadIdx.y;
    #pragma unroll
    for (int i = 0; i < 32; i += 8)
        tile[ty + i][tx] = W1[(size_t)(k0 + ty + i) * HDIM + n0 + tx];
    __syncthreads();
    #pragma unroll
    for (int i = 0; i < 32; i += 8) {
        __nv_fp8_storage_t v = __nv_cvt_float_to_fp8(tile[tx][ty + i],
                                                     __NV_SATFINITE, __NV_E4M3);
        g_w1t[(size_t)(n0 + ty + i) * SDIM + k0 + tx] = (uint8_t)v;
    }
}

// ---------------- main persistent kernel ----------------
extern "C" __global__ void __launch_bounds__(THREADS, 1)
traj_main(const int* __restrict__ lengths, const float* __restrict__ b1,
          const float* __restrict__ W2)
{
    extern __shared__ __align__(1024) char smem[];
    float*    logitsS = (float*)(smem + LOG_OFF);
    unsigned* itemS   = (unsigned*)(smem + ITEM_OFF);
    const uint32_t smem_u = smem_u32(smem);

    const int tid  = threadIdx.x;
    const int lane = tid & 31;
    const int wid  = tid >> 5;
    const int warp_m = wid & 3;          // 4 row-groups of 32 (128 rows)
    const int warp_n = wid >> 2;         // 4 col-groups of 64 (256 cols)
    const int m0  = warp_m * 32;
    const int n0w = warp_n * 64;

    // loop-invariant cp.async offsets (A: 2x16B, B: 4x16B per thread)
    const int rowT = tid >> 3, kgT = tid & 7;       // rowT 0..63
    uint32_t dstA[2], dstB[4];
    int srcA[2], srcB[4];
    #pragma unroll
    for (int i = 0; i < 2; ++i) {                    // rows rowT + 64i (0..127)
        srcA[i] = (rowT + i * 64) * SDIM + kgT * 16;
        dstA[i] = SW128((rowT + i * 64) * 128 + kgT * 16);
    }
    #pragma unroll
    for (int i = 0; i < 4; ++i) {                    // rows rowT + 64i (0..255)
        srcB[i] = (rowT + i * 64) * SDIM + kgT * 16;
        dstB[i] = SW128((rowT + i * 64) * 128 + kgT * 16);
    }

    // LDSM swizzled base offsets (ks=0); per-ks: ^ (ks<<5)
    uint32_t offA[2], offB[4];
    #pragma unroll
    for (int mi = 0; mi < 2; ++mi)
        offA[mi] = SW128((m0 + mi * 16 + (lane & 15)) * 128 + (lane >> 4) * 16);
    #pragma unroll
    for (int nj = 0; nj < 4; ++nj)
        offB[nj] = SW128((n0w + nj * 16 + (lane & 15)) * 128 + (lane >> 4) * 16);

    for (;;) {
        if (tid == 0) itemS[0] = atomicAdd(&g_counter, 1u);
        __syncthreads();
        const unsigned item = itemS[0];
        __syncthreads();
        if (item >= NITEMS) break;
        // nt in HIGH bits (R11-proven ordering)
        const int nt   = item >> 8;
        const int rem  = item & 255;
        const int b    = rem >> 2;
        const int tile = rem & 3;
        const int t_base = tile * MT;
        const int len = lengths[b];
        if (t_base >= len) continue;

        if (tid < 512) logitsS[tid] = 0.f;           // 128 rows x 4 actions

        const uint8_t* abase = g_sbf + ((size_t)b * TP1 + t_base) * SDIM;
        const uint8_t* bbase = g_w1t + (size_t)nt * NT * SDIM;

        float d[2][8][4];
        #pragma unroll
        for (int mi = 0; mi < 2; ++mi)
            #pragma unroll
            for (int ni = 0; ni < 8; ++ni)
                #pragma unroll
                for (int k = 0; k < 4; ++k) d[mi][ni][k] = 0.f;

        // ---- preload chunks 0..2 into stages 0..2 ----
        #pragma unroll
        for (int pc = 0; pc < 3; ++pc) {
            const int koff = pc * KC;
            #pragma unroll
            for (int i = 0; i < 2; ++i)
                cp16(smem_u + A_OFF(pc) + dstA[i], abase + koff + srcA[i]);
            #pragma unroll
            for (int i = 0; i < 4; ++i)
                cp16(smem_u + B_OFF(pc) + dstB[i], bbase + koff + srcB[i]);
            asm volatile("cp.async.commit_group;");
        }

        for (int c = 0; c < NCHUNK; ++c) {
            // require group for chunk c complete; ≤2 newer groups may remain
            if (c < 6)       asm volatile("cp.async.wait_group 2;");
            else if (c == 6) asm volatile("cp.async.wait_group 1;");
            else             asm volatile("cp.async.wait_group 0;");
            __syncthreads();     // single barrier per chunk

            const int st = c & (NSTAGE - 1);
            const uint32_t aS = smem_u + A_OFF(st);
            const uint32_t bS = smem_u + B_OFF(st);
            #pragma unroll
            for (int ks = 0; ks < 4; ++ks) {
                const uint32_t kx = (uint32_t)(ks << 5);
                uint32_t afr[2][4];
                #pragma unroll
                for (int mi = 0; mi < 2; ++mi)
                    ldsm_x4(afr[mi], aS + (offA[mi] ^ kx));
                uint32_t bq[4][4];
                #pragma unroll
                for (int nj = 0; nj < 4; ++nj)
                    ldsm_x4(bq[nj], bS + (offB[nj] ^ kx));
                #pragma unroll
                for (int mi = 0; mi < 2; ++mi)
                    #pragma unroll
                    for (int nj = 0; nj < 4; ++nj) {
                        mma16832(d[mi][2*nj],   afr[mi], bq[nj][0], bq[nj][2]);
                        mma16832(d[mi][2*nj+1], afr[mi], bq[nj][1], bq[nj][3]);
                    }
            }

            // prefetch chunk c+3 into stage (c+3)&3 — its previous readers
            // (chunk c-1) all passed this iteration's top barrier.
            if (c + 3 < NCHUNK) {
                const int ps = (c + 3) & (NSTAGE - 1);
                const int koff = (c + 3) * KC;
                #pragma unroll
                for (int i = 0; i < 2; ++i)
                    cp16(smem_u + A_OFF(ps) + dstA[i], abase + koff + srcA[i]);
                #pragma unroll
                for (int i = 0; i < 4; ++i)
                    cp16(smem_u + B_OFF(ps) + dstB[i], bbase + koff + srcB[i]);
                asm volatile("cp.async.commit_group;");
            }
        }

        // ---- fused epilogue: relu(acc+b1) . W2[:,0:4] ----
        float plog[4][4];
        #pragma unroll
        for (int i = 0; i < 4; ++i)
            #pragma unroll
            for (int a = 0; a < 4; ++a) plog[i][a] = 0.f;

        #pragma unroll
        for (int ni = 0; ni < 8; ++ni) {
            #pragma unroll
            for (int jc = 0; jc < 2; ++jc) {
                int col = nt * NT + n0w + ni * 8 + 2 * (lane & 3) + jc;
                float bias = __ldg(b1 + col);
                float4 w2v = *(const float4*)(W2 + (size_t)col * 32);
                #pragma unroll
                for (int mi = 0; mi < 2; ++mi) {
                    #pragma unroll
                    for (int half = 0; half < 2; ++half) {
                        float h = d[mi][ni][half * 2 + jc] + bias;
                        h = fmaxf(h, 0.f);
                        int slot = mi * 2 + half;
                        plog[slot][0] += h * w2v.x;
                        plog[slot][1] += h * w2v.y;
                        plog[slot][2] += h * w2v.z;
                        plog[slot][3] += h * w2v.w;
                    }
                }
            }
        }

        __syncthreads();   // logitsS zeroing (item top) visible to all before atomics
        #pragma unroll
        for (int slot = 0; slot < 4; ++slot) {
            int row = m0 + (slot >> 1) * 16 + (slot & 1) * 8 + (lane >> 2);
            #pragma unroll
            for (int a = 0; a < 4; ++a)
                atomicAdd(&logitsS[row * 4 + a], plog[slot][a]);
        }
        __syncthreads();
        if (tid < MT) {
            float* gl = g_logits + ((size_t)b * TP1 + t_base + tid) * 4;
            #pragma unroll
            for (int a = 0; a < 4; ++a)
                atomicAdd(gl + a, logitsS[tid * 4 + a]);
        }
    }
}

// ---------------- post: softmax + gather + masked sum per batch ----------------
extern "C" __global__ void traj_post(const int* __restrict__ actions,
                                     const int* __restrict__ lengths,
                                     const float* __restrict__ b2)
{
    const int b = blockIdx.x;
    const int tid = threadIdx.x;
    const int len = lengths[b];
    const float bb0 = b2[0], bb1 = b2[1], bb2 = b2[2], bb3 = b2[3];
    float acc = 0.f;
    for (int t = tid; t < len; t += 256) {
        const float4 z4 = *(const float4*)(g_logits + ((size_t)b * TP1 + t) * 4);
        float z[4] = { z4.x + bb0, z4.y + bb1, z4.z + bb2, z4.w + bb3 };
        float zm = fmaxf(fmaxf(z[0], z[1]), fmaxf(z[2], z[3]));
        float se = expf(z[0]-zm) + expf(z[1]-zm) + expf(z[2]-zm) + expf(z[3]-zm);
        float lse = zm + logf(se);
        int act = actions[b * MAXT + t];
        acc += z[act] - lse;
    }
    #pragma unroll
    for (int off = 16; off > 0; off >>= 1)
        acc += __shfl_xor_sync(0xffffffffu, acc, off);
    __shared__ float red[8];
    if ((tid & 31) == 0) red[tid >> 5] = acc;
    __syncthreads();
    if (tid == 0) {
        float s = 0.f;
        #pragma unroll
        for (int w = 0; w < 8; ++w) s += red[w];
        g_post[b] = s;
    }
}

extern "C" __global__ void traj_reduce(float* __restrict__ out)
{
    __shared__ float sm[BB];
    int i = threadIdx.x;
    sm[i] = g_post[i];
    __syncthreads();
    for (int off = BB / 2; off > 0; off >>= 1) {
        if (i < off) sm[i] += sm[i + off];
        __syncthreads();
    }
    if (i == 0) out[0] = -sm[0];
}

extern "C" void kernel_launch(void* const* d_in, const int* in_sizes, int n_in,
                              void* d_out, int out_size)
{
    const float* s_in    = (const float*)d_in[0];
    const int*   actions = (const int*)  d_in[1];
    const int*   lengths = (const int*)  d_in[2];
    const float* W1      = (const float*)d_in[3];
    const float* b1      = (const float*)d_in[4];
    const float* W2      = (const float*)d_in[5];
    const float* b2      = (const float*)d_in[6];
    float* out = (float*)d_out;

    cudaFuncSetAttribute(traj_main, cudaFuncAttributeMaxDynamicSharedMemorySize, SMEM_BYTES);

    init_counter<<<1, 1>>>();
    zero_logits<<<512, 256>>>();
    s_cvt<<<(BB * TP1 * SDIM / 16) / 256, 256>>>(s_in);
    w1_transpose<<<dim3(HDIM / 32, SDIM / 32), dim3(32, 8)>>>(W1);
    traj_main<<<GRID, THREADS, SMEM_BYTES>>>(lengths, b1, W2);
    traj_post<<<BB, 256>>>(actions, lengths, b2);
    traj_reduce<<<1, BB>>>(out);
}

// round 15
// speedup vs baseline: 1.8622x; 1.8622x over previous
#include <cuda_runtime.h>
#include <cuda_bf16.h>
#include <cuda_fp8.h>
#include <math.h>
#include <stdint.h>

// Problem constants
#define BB    64
#define MAXT  511
#define TP1   512
#define SDIM  1024
#define HDIM  4096

// Tiling (fp8: KC = 128 k-elements = 128 bytes per row-chunk)
#define MT       64
#define TILES_PER_B 8
#define KC       128
#define NCHUNK   (SDIM/KC)            // 8 chunks per nt
#define NT       256                  // H cols per n-tile
#define NNT      (HDIM/NT)            // 16
#define NITEMS   (NNT*BB*TILES_PER_B) // 8192 items: (nt, b, tile) nt-major
#define THREADS  256                  // 8 warps, each 32x64
#define GRID     296                  // persistent CTAs (2/SM)

// SMEM layout (bytes) — same as R13
#define A_OFF(b)  ((b)*8192)              // 2 x 8 KB   (64 rows x 128B)
#define B_OFF(b)  (16384 + (b)*32768)     // 2 x 32 KB  (256 rows x 128B)
#define LOG_OFF   81920
#define ITEM_OFF  82944
#define SMEM_BYTES 83072

#define SW128(x) ((x) ^ (((x) >> 3) & 0x70))

__device__ uint8_t g_sbf[(size_t)BB * TP1 * SDIM];   // 33.5 MB: s in e4m3
__device__ uint8_t g_w1t[(size_t)HDIM * SDIM];       // 4 MB  : W1^T e4m3
__device__ float   g_logits[(size_t)BB * TP1 * 4];   // 512 KB partial logits
__device__ float   g_post[BB];
__device__ unsigned g_counter;

// ---------------- helpers ----------------
__device__ __forceinline__ uint32_t smem_u32(const void* p) {
    uint32_t a;
    asm("{ .reg .u64 t; cvta.to.shared.u64 t, %1; cvt.u32.u64 %0, t; }" : "=r"(a) : "l"(p));
    return a;
}
__device__ __forceinline__ uint32_t fp8x4(float a, float b, float c, float d) {
    __nv_fp8x2_storage_t lo = __nv_cvt_float2_to_fp8x2(make_float2(a, b),
                                                       __NV_SATFINITE, __NV_E4M3);
    __nv_fp8x2_storage_t hi = __nv_cvt_float2_to_fp8x2(make_float2(c, d),
                                                       __NV_SATFINITE, __NV_E4M3);
    return (uint32_t)lo | ((uint32_t)hi << 16);
}
__device__ __forceinline__ void cp16(uint32_t dst, const void* src) {
    asm volatile("cp.async.cg.shared.global [%0], [%1], 16;" :: "r"(dst), "l"(src));
}
__device__ __forceinline__ void ldsm_x4(uint32_t* r, uint32_t addr) {
    asm volatile("ldmatrix.sync.aligned.m8n8.x4.shared.b16 {%0,%1,%2,%3}, [%4];"
                 : "=r"(r[0]), "=r"(r[1]), "=r"(r[2]), "=r"(r[3]) : "r"(addr));
}
__device__ __forceinline__ void mma16832(float* d, const uint32_t* a,
                                         uint32_t b0, uint32_t b1) {
    asm volatile("mma.sync.aligned.m16n8k32.row.col.f32.e4m3.e4m3.f32 "
                 "{%0,%1,%2,%3}, {%4,%5,%6,%7}, {%8,%9}, {%0,%1,%2,%3};"
                 : "+f"(d[0]), "+f"(d[1]), "+f"(d[2]), "+f"(d[3])
                 : "r"(a[0]), "r"(a[1]), "r"(a[2]), "r"(a[3]), "r"(b0), "r"(b1));
}

// ---------------- prepass kernels ----------------
extern "C" __global__ void init_counter() { g_counter = 0u; }

extern "C" __global__ void zero_logits() {
    ((float4*)g_logits)[blockIdx.x * 256 + threadIdx.x] = make_float4(0.f, 0.f, 0.f, 0.f);
}

extern "C" __global__ void s_cvt(const float* __restrict__ s) {
    size_t i = (size_t)blockIdx.x * 256 + threadIdx.x;
    const float4* p = (const float4*)s + i * 4;
    float4 v0 = p[0], v1 = p[1], v2 = p[2], v3 = p[3];
    uint4 o;
    o.x = fp8x4(v0.x, v0.y, v0.z, v0.w);
    o.y = fp8x4(v1.x, v1.y, v1.z, v1.w);
    o.z = fp8x4(v2.x, v2.y, v2.z, v2.w);
    o.w = fp8x4(v3.x, v3.y, v3.z, v3.w);
    ((uint4*)g_sbf)[i] = o;
}

extern "C" __global__ void w1_transpose(const float* __restrict__ W1) {
    __shared__ float tile[32][33];
    int n0 = blockIdx.x * 32, k0 = blockIdx.y * 32;
    int tx = threadIdx.x, ty = threadIdx.y;
    #pragma unroll
    for (int i = 0; i < 32; i += 8)
        tile[ty + i][tx] = W1[(size_t)(k0 + ty + i) * HDIM + n0 + tx];
    __syncthreads();
    #pragma unroll
    for (int i = 0; i < 32; i += 8) {
        __nv_fp8_storage_t v = __nv_cvt_float_to_fp8(tile[tx][ty + i],
                                                     __NV_SATFINITE, __NV_E4M3);
        g_w1t[(size_t)(n0 + ty + i) * SDIM + k0 + tx] = (uint8_t)v;
    }
}

// ---------------- main persistent kernel ----------------
extern "C" __global__ void __launch_bounds__(THREADS, 2)
traj_main(const int* __restrict__ lengths, const float* __restrict__ b1,
          const float* __restrict__ W2)
{
    extern __shared__ __align__(1024) char smem[];
    float*    logitsS = (float*)(smem + LOG_OFF);
    unsigned* itemS   = (unsigned*)(smem + ITEM_OFF);
    const uint32_t smem_u = smem_u32(smem);

    const int tid  = threadIdx.x;
    const int lane = tid & 31;
    const int wid  = tid >> 5;
    const int warp_m = wid & 1;
    const int warp_n = wid >> 1;
    const int m0  = warp_m * 32;
    const int n0w = warp_n * 64;

    // Single-base addresses; per-piece strides are swizzle-transparent:
    //   SW128(x + k*4096) = SW128(x) + k*4096  (A/B row groups)
    //   SW128(x + k*2048) = SW128(x) + k*2048  (LDSM mi/nj groups)
    const int rowT = tid >> 3, kgT = tid & 7;       // rowT 0..31
    const int src0 = rowT * SDIM + kgT * 16;        // gmem byte offset base
    const uint32_t dst0 = SW128(rowT * 128 + kgT * 16);
    const uint32_t offA0 = SW128((m0 + (lane & 15)) * 128 + (lane >> 4) * 16);
    const uint32_t offB0 = SW128((n0w + (lane & 15)) * 128 + (lane >> 4) * 16);

    for (;;) {
        if (tid == 0) itemS[0] = atomicAdd(&g_counter, 1u);
        __syncthreads();
        const unsigned item = itemS[0];
        __syncthreads();
        if (item >= NITEMS) break;
        // nt in HIGH bits (R11-proven ordering)
        const int nt   = item >> 9;
        const int rem  = item & 511;
        const int b    = rem >> 3;
        const int tile = rem & 7;
        const int t_base = tile * MT;
        const int len = lengths[b];
        if (t_base >= len) continue;

        logitsS[tid] = 0.f;

        const uint8_t* abase = g_sbf + ((size_t)b * TP1 + t_base) * SDIM + src0;
        const uint8_t* bbase = g_w1t + (size_t)nt * NT * SDIM + src0;

        float d[2][8][4];
        #pragma unroll
        for (int mi = 0; mi < 2; ++mi)
            #pragma unroll
            for (int ni = 0; ni < 8; ++ni)
                #pragma unroll
                for (int k = 0; k < 4; ++k) d[mi][ni][k] = 0.f;

        // ---- preload chunk 0 ----
        #pragma unroll
        for (int i = 0; i < 2; ++i)
            cp16(smem_u + A_OFF(0) + dst0 + i * 4096, abase + i * 32 * SDIM);
        #pragma unroll
        for (int i = 0; i < 8; ++i)
            cp16(smem_u + B_OFF(0) + dst0 + i * 4096, bbase + i * 32 * SDIM);
        asm volatile("cp.async.commit_group;");

        for (int c = 0; c < NCHUNK; ++c) {
            if (c + 1 < NCHUNK) {
                const int nb = (c + 1) & 1, koff = (c + 1) * KC;
                #pragma unroll
                for (int i = 0; i < 2; ++i)
                    cp16(smem_u + A_OFF(nb) + dst0 + i * 4096,
                         abase + koff + i * 32 * SDIM);
                #pragma unroll
                for (int i = 0; i < 8; ++i)
                    cp16(smem_u + B_OFF(nb) + dst0 + i * 4096,
                         bbase + koff + i * 32 * SDIM);
                asm volatile("cp.async.commit_group;");
                asm volatile("cp.async.wait_group 1;");
            } else {
                asm volatile("cp.async.wait_group 0;");
            }
            __syncthreads();

            const uint32_t aS = smem_u + A_OFF(c & 1);
            const uint32_t bS = smem_u + B_OFF(c & 1);

            // ---- fragment-pipelined ks loop: bq double-buffered 1 ks ahead ----
            uint32_t bq0[4][4], bq1[4][4];
            {   // bq for ks=0
                const uint32_t bB = bS + offB0;
                #pragma unroll
                for (int nj = 0; nj < 4; ++nj)
                    ldsm_x4(bq0[nj], bB + nj * 2048);
            }
            #pragma unroll
            for (int ks = 0; ks < 4; ++ks) {
                const uint32_t kx = (uint32_t)(ks << 5);
                uint32_t afr[2][4];
                {
                    const uint32_t aB = aS + (offA0 ^ kx);
                    #pragma unroll
                    for (int mi = 0; mi < 2; ++mi)
                        ldsm_x4(afr[mi], aB + mi * 2048);
                }
                uint32_t (*cur)[4] = (ks & 1) ? bq1 : bq0;
                uint32_t (*nxt)[4] = (ks & 1) ? bq0 : bq1;
                if (ks < 3) {   // prefetch bq(ks+1) before the MMAs of ks
                    const uint32_t bB = bS + (offB0 ^ (uint32_t)((ks + 1) << 5));
                    #pragma unroll
                    for (int nj = 0; nj < 4; ++nj)
                        ldsm_x4(nxt[nj], bB + nj * 2048);
                }
                #pragma unroll
                for (int mi = 0; mi < 2; ++mi)
                    #pragma unroll
                    for (int nj = 0; nj < 4; ++nj) {
                        mma16832(d[mi][2*nj],   afr[mi], cur[nj][0], cur[nj][2]);
                        mma16832(d[mi][2*nj+1], afr[mi], cur[nj][1], cur[nj][3]);
                    }
            }
            __syncthreads();
        }

        // ---- fused epilogue: relu(acc+b1) . W2[:,0:4] ----
        float plog[4][4];
        #pragma unroll
        for (int i = 0; i < 4; ++i)
            #pragma unroll
            for (int a = 0; a < 4; ++a) plog[i][a] = 0.f;

        #pragma unroll
        for (int ni = 0; ni < 8; ++ni) {
            #pragma unroll
            for (int jc = 0; jc < 2; ++jc) {
                int col = nt * NT + n0w + ni * 8 + 2 * (lane & 3) + jc;
                float bias = __ldg(b1 + col);
                float4 w2v = *(const float4*)(W2 + (size_t)col * 32);
                #pragma unroll
                for (int mi = 0; mi < 2; ++mi) {
                    #pragma unroll
                    for (int half = 0; half < 2; ++half) {
                        float h = d[mi][ni][half * 2 + jc] + bias;
                        h = fmaxf(h, 0.f);
                        int slot = mi * 2 + half;
                        plog[slot][0] += h * w2v.x;
                        plog[slot][1] += h * w2v.y;
                        plog[slot][2] += h * w2v.z;
                        plog[slot][3] += h * w2v.w;
                    }
                }
            }
        }

        #pragma unroll
        for (int slot = 0; slot < 4; ++slot) {
            int row = m0 + (slot >> 1) * 16 + (slot & 1) * 8 + (lane >> 2);
            #pragma unroll
            for (int a = 0; a < 4; ++a)
                atomicAdd(&logitsS[row * 4 + a], plog[slot][a]);
        }
        __syncthreads();
        if (tid < MT) {
            float* gl = g_logits + ((size_t)b * TP1 + t_base + tid) * 4;
            #pragma unroll
            for (int a = 0; a < 4; ++a)
                atomicAdd(gl + a, logitsS[tid * 4 + a]);
        }
    }
}

// ---------------- post: softmax + gather + masked sum per batch ----------------
extern "C" __global__ void traj_post(const int* __restrict__ actions,
                                     const int* __restrict__ lengths,
                                     const float* __restrict__ b2)
{
    const int b = blockIdx.x;
    const int tid = threadIdx.x;
    const int len = lengths[b];
    const float bb0 = b2[0], bb1 = b2[1], bb2 = b2[2], bb3 = b2[3];
    float acc = 0.f;
    for (int t = tid; t < len; t += 256) {
        const float4 z4 = *(const float4*)(g_logits + ((size_t)b * TP1 + t) * 4);
        float z[4] = { z4.x + bb0, z4.y + bb1, z4.z + bb2, z4.w + bb3 };
        float zm = fmaxf(fmaxf(z[0], z[1]), fmaxf(z[2], z[3]));
        float se = expf(z[0]-zm) + expf(z[1]-zm) + expf(z[2]-zm) + expf(z[3]-zm);
        float lse = zm + logf(se);
        int act = actions[b * MAXT + t];
        acc += z[act] - lse;
    }
    #pragma unroll
    for (int off = 16; off > 0; off >>= 1)
        acc += __shfl_xor_sync(0xffffffffu, acc, off);
    __shared__ float red[8];
    if ((tid & 31) == 0) red[tid >> 5] = acc;
    __syncthreads();
    if (tid == 0) {
        float s = 0.f;
        #pragma unroll
        for (int w = 0; w < 8; ++w) s += red[w];
        g_post[b] = s;
    }
}

extern "C" __global__ void traj_reduce(float* __restrict__ out)
{
    __shared__ float sm[BB];
    int i = threadIdx.x;
    sm[i] = g_post[i];
    __syncthreads();
    for (int off = BB / 2; off > 0; off >>= 1) {
        if (i < off) sm[i] += sm[i + off];
        __syncthreads();
    }
    if (i == 0) out[0] = -sm[0];
}

extern "C" void kernel_launch(void* const* d_in, const int* in_sizes, int n_in,
                              void* d_out, int out_size)
{
    const float* s_in    = (const float*)d_in[0];
    const int*   actions = (const int*)  d_in[1];
    const int*   lengths = (const int*)  d_in[2];
    const float* W1      = (const float*)d_in[3];
    const float* b1      = (const float*)d_in[4];
    const float* W2      = (const float*)d_in[5];
    const float* b2      = (const float*)d_in[6];
    float* out = (float*)d_out;

    cudaFuncSetAttribute(traj_main, cudaFuncAttributeMaxDynamicSharedMemorySize, SMEM_BYTES);

    init_counter<<<1, 1>>>();
    zero_logits<<<512, 256>>>();
    s_cvt<<<(BB * TP1 * SDIM / 16) / 256, 256>>>(s_in);
    w1_transpose<<<dim3(HDIM / 32, SDIM / 32), dim3(32, 8)>>>(W1);
    traj_main<<<GRID, THREADS, SMEM_BYTES>>>(lengths, b1, W2);
    traj_post<<<BB, 256>>>(actions, lengths, b2);
    traj_reduce<<<1, BB>>>(out);
}